// round 4
// baseline (speedup 1.0000x reference)
#include <cuda_runtime.h>
#include <cstdint>
#include <cstddef>

// ---------------- problem constants ----------------
#define B_      128
#define C_      64
#define HW_     3136
#define M_      6
#define D_      192
#define HEADS_  8
#define INNER_  512
#define ROWS_   48          // HEADS_*M_
#define NSPLIT  4
#define LEN_    784         // HW_/NSPLIT
#define TILE_N  128
#define NTILES  7           // ceil(784/128), last tile has 16 valid cols
#define XS_STRIDE 130       // 128 + 2 pad (keeps 8B align, phase1 LDS conflict-free, phase3 2-way)
#define NEG_INF (-3.0e38f)

#define SMEM_FLOATS (6144 + 64*XS_STRIDE + ROWS_*TILE_N + 3*ROWS_)
#define SMEM_BYTES  (SMEM_FLOATS * 4)

// ---------------- scratch (__device__ globals: no allocation allowed) ----------------
__device__ float g_qbuf[B_ * M_ * INNER_];              // 1.5 MB, q pre-scaled by C^-0.5
__device__ float g_pm[B_ * ROWS_ * NSPLIT];             // per-split running max
__device__ float g_pl[B_ * ROWS_ * NSPLIT];             // per-split running sum
__device__ float g_po[(size_t)B_ * ROWS_ * NSPLIT * C_];// per-split unnormalized O (6.3 MB)

typedef unsigned long long u64;

// ---------------- packed f32x2 helpers (Blackwell; ptxas won't auto-fuse) ----------------
__device__ __forceinline__ void ffma2(u64 &d, u64 a, u64 b) {
    asm("fma.rn.f32x2 %0, %1, %2, %0;" : "+l"(d) : "l"(a), "l"(b));
}
__device__ __forceinline__ u64 fmul2(u64 a, u64 b) {
    u64 d; asm("mul.rn.f32x2 %0, %1, %2;" : "=l"(d) : "l"(a), "l"(b)); return d;
}
__device__ __forceinline__ u64 pack2(float lo, float hi) {
    return ((u64)__float_as_uint(hi) << 32) | (u64)__float_as_uint(lo);
}
__device__ __forceinline__ float lo2(u64 v) { return __uint_as_float((unsigned)v); }
__device__ __forceinline__ float hi2(u64 v) { return __uint_as_float((unsigned)(v >> 32)); }

// ============================================================================
// Kernel 1: q = (z @ Wq + bq) * C^-0.5   -> g_qbuf [B][M][INNER]
// 48 blocks x 16 rows each so Wq (393KB) is read once per block (19MB total).
// ============================================================================
__global__ void __launch_bounds__(256) qproj_kernel(
    const float* __restrict__ z, const float* __restrict__ Wq,
    const float* __restrict__ bq)
{
    __shared__ float zsh[16 * 192];
    const int t  = threadIdx.x;
    const int e0 = blockIdx.x * 16;   // row = (b,m) linear index

    for (int idx = t; idx < 16 * 192; idx += 256)
        zsh[idx] = z[(size_t)e0 * 192 + idx];
    __syncthreads();

    const int i0 = t, i1 = t + 256;
    float acc0[16], acc1[16];
#pragma unroll
    for (int r = 0; r < 16; r++) { acc0[r] = 0.f; acc1[r] = 0.f; }

    for (int k = 0; k < 192; k++) {
        float w0 = Wq[k * 512 + i0];
        float w1 = Wq[k * 512 + i1];
#pragma unroll
        for (int r = 0; r < 16; r++) {
            float zv = zsh[r * 192 + k];
            acc0[r] += zv * w0;
            acc1[r] += zv * w1;
        }
    }
    const float b0 = bq[i0], b1 = bq[i1];
#pragma unroll
    for (int r = 0; r < 16; r++) {
        g_qbuf[(size_t)(e0 + r) * 512 + i0] = (acc0[r] + b0) * 0.125f;
        g_qbuf[(size_t)(e0 + r) * 512 + i1] = (acc1[r] + b1) * 0.125f;
    }
}

// ============================================================================
// Kernel 2: fused attention, flash-decoding over HW. grid (NSPLIT, B), 256 thr.
// Per tile: phase1 S=Q@X (f32x2 over n-pairs) -> phase2 online softmax ->
// phase3 O += P@X^T (f32x2 dot over n-pairs; hadd deferred to epilogue).
// NOTE: torch .view(B,heads,M,C) is a FLAT reshape of [B, M, heads*C], so
// q row r (= h*6+m), channel c is simply qflat[b*3072 + r*64 + c].
// ============================================================================
__global__ void __launch_bounds__(256, 2) attn_kernel(const float* __restrict__ x)
{
    extern __shared__ float sm[];
    float* qs2 = sm;                        // 48*64 duplicated pairs -> 6144 floats
    float* xs  = sm + 6144;                 // 64 * XS_STRIDE
    float* ss  = xs + 64 * XS_STRIDE;       // 48 * 128
    float* smm = ss + ROWS_ * TILE_N;       // 48
    float* sml = smm + ROWS_;               // 48
    float* smc = sml + ROWS_;               // 48

    const int t     = threadIdx.x;
    const int split = blockIdx.x;
    const int b     = blockIdx.y;
    const int n0    = split * LEN_;
    const int rg    = t >> 5;               // warp id = row-group (6 rows)
    const int lane  = t & 31;

    if (t < ROWS_) { smm[t] = NEG_INF; sml[t] = 0.f; }

    u64* qs2v = (u64*)qs2;
    for (int e = t; e < ROWS_ * C_; e += 256) {
        // flat-view mapping: q[b, h, m, c] = qflat[b][h*M*C + m*C + c] = qflat[b][r*64+c] = qflat[b][e]
        float qv = g_qbuf[(size_t)b * (ROWS_ * C_) + e];
        qs2v[e] = pack2(qv, qv);            // duplicated so phase1 needs no packing
    }

    u64 oacc[6][2];
#pragma unroll
    for (int i = 0; i < 6; i++) { oacc[i][0] = 0ull; oacc[i][1] = 0ull; }
    __syncthreads();

    for (int tile = 0; tile < NTILES; tile++) {
        const int t0 = tile * TILE_N;

        // ---- load x tile [64 c][128 n] (zero-pad past split end) ----
#pragma unroll
        for (int it = 0; it < 8; it++) {
            int idx4 = t + it * 256;
            int c = idx4 >> 5, j4 = idx4 & 31;
            int nl = j4 * 4;
            float4 v = make_float4(0.f, 0.f, 0.f, 0.f);
            if (t0 + nl < LEN_)
                v = *(const float4*)&x[((size_t)b * C_ + c) * HW_ + n0 + t0 + nl];
            *(float2*)&xs[c * XS_STRIDE + nl]     = make_float2(v.x, v.y);
            *(float2*)&xs[c * XS_STRIDE + nl + 2] = make_float2(v.z, v.w);
        }
        __syncthreads();

        // ---- phase 1: S[48][128] = Q @ Xtile ----
        {
            u64 sacc[6][2];
#pragma unroll
            for (int i = 0; i < 6; i++) { sacc[i][0] = 0ull; sacc[i][1] = 0ull; }
            const int nb = lane * 4;
#pragma unroll 4
            for (int c = 0; c < 64; c++) {
                u64 xv0 = *(const u64*)&xs[c * XS_STRIDE + nb];
                u64 xv1 = *(const u64*)&xs[c * XS_STRIDE + nb + 2];
#pragma unroll
                for (int i = 0; i < 6; i++) {
                    u64 qv = qs2v[(rg * 6 + i) * 64 + c];
                    ffma2(sacc[i][0], qv, xv0);
                    ffma2(sacc[i][1], qv, xv1);
                }
            }
#pragma unroll
            for (int i = 0; i < 6; i++) {
                int r = rg * 6 + i;
                *(float2*)&ss[r * TILE_N + nb]     = make_float2(lo2(sacc[i][0]), hi2(sacc[i][0]));
                *(float2*)&ss[r * TILE_N + nb + 2] = make_float2(lo2(sacc[i][1]), hi2(sacc[i][1]));
            }
        }
        __syncthreads();

        // ---- phase 2: online softmax (warp rg owns rows rg*6..rg*6+5) ----
        {
            const int vlim = LEN_ - t0;   // local n < vlim is valid
#pragma unroll
            for (int i = 0; i < 6; i++) {
                int r = rg * 6 + i;
                float v0 = (lane      < vlim) ? ss[r * TILE_N + lane]      : NEG_INF;
                float v1 = (lane + 32 < vlim) ? ss[r * TILE_N + lane + 32] : NEG_INF;
                float v2 = (lane + 64 < vlim) ? ss[r * TILE_N + lane + 64] : NEG_INF;
                float v3 = (lane + 96 < vlim) ? ss[r * TILE_N + lane + 96] : NEG_INF;
                float ml = fmaxf(fmaxf(v0, v1), fmaxf(v2, v3));
#pragma unroll
                for (int off = 16; off; off >>= 1)
                    ml = fmaxf(ml, __shfl_xor_sync(0xffffffffu, ml, off));
                float mprev = smm[r];
                float mnew  = fmaxf(mprev, ml);
                float cr    = __expf(mprev - mnew);
                float p0 = __expf(v0 - mnew);   // invalid lanes: exp(-3e38-..) == 0
                float p1 = __expf(v1 - mnew);
                float p2 = __expf(v2 - mnew);
                float p3 = __expf(v3 - mnew);
                ss[r * TILE_N + lane]      = p0;
                ss[r * TILE_N + lane + 32] = p1;
                ss[r * TILE_N + lane + 64] = p2;
                ss[r * TILE_N + lane + 96] = p3;
                float sl = (p0 + p1) + (p2 + p3);
#pragma unroll
                for (int off = 16; off; off >>= 1)
                    sl += __shfl_xor_sync(0xffffffffu, sl, off);
                if (lane == 0) {
                    sml[r] = sml[r] * cr + sl;
                    smm[r] = mnew;
                    smc[r] = cr;
                }
            }
        }
        __syncthreads();

        // ---- phase 3: O[48][64] = O*corr + P @ Xtile^T (packed over n-pairs) ----
        {
#pragma unroll
            for (int i = 0; i < 6; i++) {
                float cr = smc[rg * 6 + i];
                u64 crd = pack2(cr, cr);
                oacc[i][0] = fmul2(oacc[i][0], crd);
                oacc[i][1] = fmul2(oacc[i][1], crd);
            }
            const int c0 = lane * 2;
#pragma unroll 2
            for (int np = 0; np < 64; np++) {
                int n = np * 2;
                u64 xv0 = *(const u64*)&xs[(c0    ) * XS_STRIDE + n];
                u64 xv1 = *(const u64*)&xs[(c0 + 1) * XS_STRIDE + n];
#pragma unroll
                for (int i = 0; i < 6; i++) {
                    u64 pv = *(const u64*)&ss[(rg * 6 + i) * TILE_N + n];
                    ffma2(oacc[i][0], pv, xv0);
                    ffma2(oacc[i][1], pv, xv1);
                }
            }
        }
        __syncthreads();
    }

    // ---- epilogue: horizontal add + write split partials ----
#pragma unroll
    for (int i = 0; i < 6; i++) {
        int r = rg * 6 + i;
        size_t base = ((size_t)(b * ROWS_ + r) * NSPLIT + split) * C_;
        g_po[base + lane * 2    ] = lo2(oacc[i][0]) + hi2(oacc[i][0]);
        g_po[base + lane * 2 + 1] = lo2(oacc[i][1]) + hi2(oacc[i][1]);
    }
    if (t < ROWS_) {
        g_pm[(b * ROWS_ + t) * NSPLIT + split] = smm[t];
        g_pl[(b * ROWS_ + t) * NSPLIT + split] = sml[t];
    }
}

// ============================================================================
// Kernel 3: combine splits + out = res @ Wo + bo + z. 48 blocks x 16 (b,m) rows.
// Output side IS a real transpose: res[b][m][h*64+c] = O[b, h*6+m, c].
// ============================================================================
__global__ void __launch_bounds__(256) outproj_kernel(
    const float* __restrict__ z, const float* __restrict__ Wo,
    const float* __restrict__ bo, float* __restrict__ out)
{
    __shared__ float res[16 * 512];
    const int t  = threadIdx.x;
    const int e0 = blockIdx.x * 16;

    if (t < 128) {                       // one (row, head) per thread
        int rl = t >> 3, h = t & 7;
        int e = e0 + rl;
        int bb = e / 6, m = e % 6;
        int r = h * 6 + m;
        int base = (bb * ROWS_ + r) * NSPLIT;
        float m0 = g_pm[base], m1 = g_pm[base + 1], m2 = g_pm[base + 2], m3 = g_pm[base + 3];
        float Mx = fmaxf(fmaxf(m0, m1), fmaxf(m2, m3));
        float w0 = __expf(m0 - Mx), w1 = __expf(m1 - Mx);
        float w2 = __expf(m2 - Mx), w3 = __expf(m3 - Mx);
        float L = g_pl[base] * w0 + g_pl[base + 1] * w1
                + g_pl[base + 2] * w2 + g_pl[base + 3] * w3;
        float rinv = 1.0f / L;
        const float* p0 = &g_po[(size_t)(base + 0) * C_];
        const float* p1 = &g_po[(size_t)(base + 1) * C_];
        const float* p2 = &g_po[(size_t)(base + 2) * C_];
        const float* p3 = &g_po[(size_t)(base + 3) * C_];
#pragma unroll 4
        for (int c = 0; c < 64; c++) {
            float v = p0[c] * w0 + p1[c] * w1 + p2[c] * w2 + p3[c] * w3;
            res[rl * 512 + h * 64 + c] = v * rinv;
        }
    }
    __syncthreads();

    if (t < 192) {                        // one output column d for 16 rows
        const int d = t;
        float acc[16];
        float bv = bo[d];
#pragma unroll
        for (int rl = 0; rl < 16; rl++)
            acc[rl] = bv + z[(size_t)(e0 + rl) * D_ + d];
        for (int i = 0; i < 512; i++) {
            float w = Wo[i * D_ + d];
#pragma unroll
            for (int rl = 0; rl < 16; rl++)
                acc[rl] += res[rl * 512 + i] * w;
        }
#pragma unroll
        for (int rl = 0; rl < 16; rl++)
            out[(size_t)(e0 + rl) * D_ + d] = acc[rl];
    }
}

// ============================================================================
extern "C" void kernel_launch(void* const* d_in, const int* in_sizes, int n_in,
                              void* d_out, int out_size)
{
    (void)in_sizes; (void)n_in; (void)out_size;
    const float* x  = (const float*)d_in[0];
    const float* z  = (const float*)d_in[1];
    const float* Wq = (const float*)d_in[2];
    const float* bq = (const float*)d_in[3];
    const float* Wo = (const float*)d_in[4];
    const float* bo = (const float*)d_in[5];
    float* out = (float*)d_out;

    // idempotent; legal during graph capture (not a stream op, not an alloc)
    cudaFuncSetAttribute(attn_kernel, cudaFuncAttributeMaxDynamicSharedMemorySize, SMEM_BYTES);

    qproj_kernel<<<48, 256>>>(z, Wq, bq);
    attn_kernel<<<dim3(NSPLIT, B_), 256, SMEM_BYTES>>>(x);
    outproj_kernel<<<48, 256>>>(z, Wo, bo, out);
}

// round 5
// speedup vs baseline: 1.2566x; 1.2566x over previous
#include <cuda_runtime.h>
#include <cstdint>
#include <cstddef>

// ---------------- problem constants ----------------
#define B_      128
#define C_      64
#define HW_     3136
#define M_      6
#define D_      192
#define HEADS_  8
#define INNER_  512
#define ROWS_   48          // HEADS_*M_
#define NSPLIT  4
#define LEN_    784         // HW_/NSPLIT
#define TILE_N  128
#define NTILES  7           // ceil(784/128), last tile has 16 valid cols
#define XS_STRIDE 130       // 128 + 2 pad
#define NEG_INF (-3.0e38f)

#define SMEM_FLOATS (6144 + 64*XS_STRIDE + ROWS_*TILE_N + 3*ROWS_)
#define SMEM_BYTES  (SMEM_FLOATS * 4)

// ---------------- scratch (__device__ globals: no allocation allowed) ----------------
__device__ float g_qbuf[B_ * M_ * INNER_];              // q pre-scaled by C^-0.5
__device__ float g_pm[B_ * ROWS_ * NSPLIT];             // per-split running max
__device__ float g_pl[B_ * ROWS_ * NSPLIT];             // per-split running sum
__device__ float g_po[(size_t)B_ * ROWS_ * NSPLIT * C_];// per-split unnormalized O

typedef unsigned long long u64;

// ---------------- packed f32x2 helpers ----------------
__device__ __forceinline__ void ffma2(u64 &d, u64 a, u64 b) {
    asm("fma.rn.f32x2 %0, %1, %2, %0;" : "+l"(d) : "l"(a), "l"(b));
}
__device__ __forceinline__ u64 fmul2(u64 a, u64 b) {
    u64 d; asm("mul.rn.f32x2 %0, %1, %2;" : "=l"(d) : "l"(a), "l"(b)); return d;
}
__device__ __forceinline__ u64 pack2(float lo, float hi) {
    return ((u64)__float_as_uint(hi) << 32) | (u64)__float_as_uint(lo);
}
__device__ __forceinline__ float lo2(u64 v) { return __uint_as_float((unsigned)v); }
__device__ __forceinline__ float hi2(u64 v) { return __uint_as_float((unsigned)(v >> 32)); }

// ============================================================================
// Kernel 1: q = (z @ Wq + bq) * C^-0.5   -> g_qbuf [768][512]
// Rewritten: grid (96 row-groups x 2 col-halves) = 192 CTAs (all SMs busy),
// 8 rows/CTA, k-loop unrolled x8 -> 8 independent LDGs in flight (MLP=8).
// ============================================================================
__global__ void __launch_bounds__(256) qproj_kernel(
    const float* __restrict__ z, const float* __restrict__ Wq,
    const float* __restrict__ bq)
{
    __shared__ float zsh[8 * 192];
    const int t  = threadIdx.x;
    const int e0 = blockIdx.x * 8;                  // row group
    const int d  = blockIdx.y * 256 + t;            // output column

    for (int idx = t; idx < 8 * 192; idx += 256)
        zsh[idx] = z[(size_t)e0 * 192 + idx];
    __syncthreads();

    float acc[8];
#pragma unroll
    for (int r = 0; r < 8; r++) acc[r] = 0.f;

    for (int k0 = 0; k0 < 192; k0 += 8) {
        float w[8];
#pragma unroll
        for (int j = 0; j < 8; j++)
            w[j] = Wq[(size_t)(k0 + j) * 512 + d];
#pragma unroll
        for (int j = 0; j < 8; j++)
#pragma unroll
            for (int r = 0; r < 8; r++)
                acc[r] += zsh[r * 192 + k0 + j] * w[j];
    }
    const float bv = bq[d];
#pragma unroll
    for (int r = 0; r < 8; r++)
        g_qbuf[(size_t)(e0 + r) * 512 + d] = (acc[r] + bv) * 0.125f;
}

// ============================================================================
// Kernel 2: fused attention, flash-decoding over HW. grid (NSPLIT, B), 256 thr.
// Phase boundaries 1->2 and 2->3 are WARP-PRIVATE (warp rg only touches ss/smm/
// sml/smc rows rg*6..rg*6+5), so only __syncwarp() is needed there. Block
// barriers remain only around the shared xs tile (load, and end-of-tile).
// ============================================================================
__global__ void __launch_bounds__(256, 2) attn_kernel(const float* __restrict__ x)
{
    extern __shared__ float sm[];
    float* qs2 = sm;                        // 48*64 duplicated pairs -> 6144 floats
    float* xs  = sm + 6144;                 // 64 * XS_STRIDE
    float* ss  = xs + 64 * XS_STRIDE;       // 48 * 128
    float* smm = ss + ROWS_ * TILE_N;       // 48
    float* sml = smm + ROWS_;               // 48
    float* smc = sml + ROWS_;               // 48

    const int t     = threadIdx.x;
    const int split = blockIdx.x;
    const int b     = blockIdx.y;
    const int n0    = split * LEN_;
    const int rg    = t >> 5;               // warp id = row-group (6 rows)
    const int lane  = t & 31;

    if (t < ROWS_) { smm[t] = NEG_INF; sml[t] = 0.f; }

    u64* qs2v = (u64*)qs2;
    for (int e = t; e < ROWS_ * C_; e += 256) {
        // flat-view mapping: q[b, h, m, c] = qflat[b][r*64+c] with r=h*6+m
        float qv = g_qbuf[(size_t)b * (ROWS_ * C_) + e];
        qs2v[e] = pack2(qv, qv);            // duplicated so phase1 needs no packing
    }

    u64 oacc[6][2];
#pragma unroll
    for (int i = 0; i < 6; i++) { oacc[i][0] = 0ull; oacc[i][1] = 0ull; }
    __syncthreads();

    for (int tile = 0; tile < NTILES; tile++) {
        const int t0 = tile * TILE_N;

        // ---- load x tile [64 c][128 n] (zero-pad past split end) ----
#pragma unroll
        for (int it = 0; it < 8; it++) {
            int idx4 = t + it * 256;
            int c = idx4 >> 5, j4 = idx4 & 31;
            int nl = j4 * 4;
            float4 v = make_float4(0.f, 0.f, 0.f, 0.f);
            if (t0 + nl < LEN_)
                v = *(const float4*)&x[((size_t)b * C_ + c) * HW_ + n0 + t0 + nl];
            *(float2*)&xs[c * XS_STRIDE + nl]     = make_float2(v.x, v.y);
            *(float2*)&xs[c * XS_STRIDE + nl + 2] = make_float2(v.z, v.w);
        }
        __syncthreads();

        // ---- phase 1: S[48][128] = Q @ Xtile ----
        {
            u64 sacc[6][2];
#pragma unroll
            for (int i = 0; i < 6; i++) { sacc[i][0] = 0ull; sacc[i][1] = 0ull; }
            const int nb = lane * 4;
#pragma unroll 4
            for (int c = 0; c < 64; c++) {
                u64 xv0 = *(const u64*)&xs[c * XS_STRIDE + nb];
                u64 xv1 = *(const u64*)&xs[c * XS_STRIDE + nb + 2];
#pragma unroll
                for (int i = 0; i < 6; i++) {
                    u64 qv = qs2v[(rg * 6 + i) * 64 + c];
                    ffma2(sacc[i][0], qv, xv0);
                    ffma2(sacc[i][1], qv, xv1);
                }
            }
#pragma unroll
            for (int i = 0; i < 6; i++) {
                int r = rg * 6 + i;
                *(float2*)&ss[r * TILE_N + nb]     = make_float2(lo2(sacc[i][0]), hi2(sacc[i][0]));
                *(float2*)&ss[r * TILE_N + nb + 2] = make_float2(lo2(sacc[i][1]), hi2(sacc[i][1]));
            }
        }
        __syncwarp();   // warp-private ss rows: no block barrier needed

        // ---- phase 2: online softmax (warp rg owns rows rg*6..rg*6+5) ----
        {
            const int vlim = LEN_ - t0;   // local n < vlim is valid
#pragma unroll
            for (int i = 0; i < 6; i++) {
                int r = rg * 6 + i;
                float v0 = (lane      < vlim) ? ss[r * TILE_N + lane]      : NEG_INF;
                float v1 = (lane + 32 < vlim) ? ss[r * TILE_N + lane + 32] : NEG_INF;
                float v2 = (lane + 64 < vlim) ? ss[r * TILE_N + lane + 64] : NEG_INF;
                float v3 = (lane + 96 < vlim) ? ss[r * TILE_N + lane + 96] : NEG_INF;
                float ml = fmaxf(fmaxf(v0, v1), fmaxf(v2, v3));
#pragma unroll
                for (int off = 16; off; off >>= 1)
                    ml = fmaxf(ml, __shfl_xor_sync(0xffffffffu, ml, off));
                float mprev = smm[r];
                float mnew  = fmaxf(mprev, ml);
                float cr    = __expf(mprev - mnew);
                float p0 = __expf(v0 - mnew);   // invalid lanes: exp(-3e38-..) == 0
                float p1 = __expf(v1 - mnew);
                float p2 = __expf(v2 - mnew);
                float p3 = __expf(v3 - mnew);
                ss[r * TILE_N + lane]      = p0;
                ss[r * TILE_N + lane + 32] = p1;
                ss[r * TILE_N + lane + 64] = p2;
                ss[r * TILE_N + lane + 96] = p3;
                float sl = (p0 + p1) + (p2 + p3);
#pragma unroll
                for (int off = 16; off; off >>= 1)
                    sl += __shfl_xor_sync(0xffffffffu, sl, off);
                if (lane == 0) {
                    sml[r] = sml[r] * cr + sl;
                    smm[r] = mnew;
                    smc[r] = cr;
                }
            }
        }
        __syncwarp();   // warp-private ss/smc rows: no block barrier needed

        // ---- phase 3: O[48][64] = O*corr + P @ Xtile^T (packed over n-pairs) ----
        {
#pragma unroll
            for (int i = 0; i < 6; i++) {
                float cr = smc[rg * 6 + i];
                u64 crd = pack2(cr, cr);
                oacc[i][0] = fmul2(oacc[i][0], crd);
                oacc[i][1] = fmul2(oacc[i][1], crd);
            }
            const int c0 = lane * 2;
#pragma unroll 2
            for (int np = 0; np < 64; np++) {
                int n = np * 2;
                u64 xv0 = *(const u64*)&xs[(c0    ) * XS_STRIDE + n];
                u64 xv1 = *(const u64*)&xs[(c0 + 1) * XS_STRIDE + n];
#pragma unroll
                for (int i = 0; i < 6; i++) {
                    u64 pv = *(const u64*)&ss[(rg * 6 + i) * TILE_N + n];
                    ffma2(oacc[i][0], pv, xv0);
                    ffma2(oacc[i][1], pv, xv1);
                }
            }
        }
        __syncthreads();   // xs about to be overwritten by next tile's load
    }

    // ---- epilogue: horizontal add + write split partials ----
#pragma unroll
    for (int i = 0; i < 6; i++) {
        int r = rg * 6 + i;
        size_t base = ((size_t)(b * ROWS_ + r) * NSPLIT + split) * C_;
        g_po[base + lane * 2    ] = lo2(oacc[i][0]) + hi2(oacc[i][0]);
        g_po[base + lane * 2 + 1] = lo2(oacc[i][1]) + hi2(oacc[i][1]);
    }
    if (t < ROWS_) {
        g_pm[(b * ROWS_ + t) * NSPLIT + split] = smm[t];
        g_pl[(b * ROWS_ + t) * NSPLIT + split] = sml[t];
    }
}

// ============================================================================
// Kernel 3: combine splits + out = res @ Wo + bo + z.
// Rewritten: 192 CTAs x 4 (b,m) rows; i-loop unrolled x8 (MLP=8).
// Output transpose: res[b][m][h*64+c] = O[b, h*6+m, c].
// ============================================================================
__global__ void __launch_bounds__(256) outproj_kernel(
    const float* __restrict__ z, const float* __restrict__ Wo,
    const float* __restrict__ bo, float* __restrict__ out)
{
    __shared__ float res[4 * 512];
    const int t  = threadIdx.x;
    const int e0 = blockIdx.x * 4;

    if (t < 64) {                        // (row, head, c-half) per thread
        int rl = t >> 4;
        int rem = t & 15;
        int h = rem >> 1, ch = rem & 1;
        int e = e0 + rl;
        int bb = e / 6, m = e % 6;
        int r = h * 6 + m;
        int base = (bb * ROWS_ + r) * NSPLIT;
        float m0 = g_pm[base], m1 = g_pm[base + 1], m2 = g_pm[base + 2], m3 = g_pm[base + 3];
        float Mx = fmaxf(fmaxf(m0, m1), fmaxf(m2, m3));
        float w0 = __expf(m0 - Mx), w1 = __expf(m1 - Mx);
        float w2 = __expf(m2 - Mx), w3 = __expf(m3 - Mx);
        float L = g_pl[base] * w0 + g_pl[base + 1] * w1
                + g_pl[base + 2] * w2 + g_pl[base + 3] * w3;
        float rinv = 1.0f / L;
        const float* p0 = &g_po[(size_t)(base + 0) * C_];
        const float* p1 = &g_po[(size_t)(base + 1) * C_];
        const float* p2 = &g_po[(size_t)(base + 2) * C_];
        const float* p3 = &g_po[(size_t)(base + 3) * C_];
#pragma unroll 4
        for (int c = ch * 32; c < ch * 32 + 32; c++) {
            float v = p0[c] * w0 + p1[c] * w1 + p2[c] * w2 + p3[c] * w3;
            res[rl * 512 + h * 64 + c] = v * rinv;
        }
    }
    __syncthreads();

    if (t < 192) {                        // one output column d for 4 rows
        const int d = t;
        float acc[4];
        float bv = bo[d];
#pragma unroll
        for (int rl = 0; rl < 4; rl++)
            acc[rl] = bv + z[(size_t)(e0 + rl) * D_ + d];
        for (int i0 = 0; i0 < 512; i0 += 8) {
            float w[8];
#pragma unroll
            for (int j = 0; j < 8; j++)
                w[j] = Wo[(size_t)(i0 + j) * D_ + d];
#pragma unroll
            for (int j = 0; j < 8; j++)
#pragma unroll
                for (int rl = 0; rl < 4; rl++)
                    acc[rl] += res[rl * 512 + i0 + j] * w[j];
        }
#pragma unroll
        for (int rl = 0; rl < 4; rl++)
            out[(size_t)(e0 + rl) * D_ + d] = acc[rl];
    }
}

// ============================================================================
extern "C" void kernel_launch(void* const* d_in, const int* in_sizes, int n_in,
                              void* d_out, int out_size)
{
    (void)in_sizes; (void)n_in; (void)out_size;
    const float* x  = (const float*)d_in[0];
    const float* z  = (const float*)d_in[1];
    const float* Wq = (const float*)d_in[2];
    const float* bq = (const float*)d_in[3];
    const float* Wo = (const float*)d_in[4];
    const float* bo = (const float*)d_in[5];
    float* out = (float*)d_out;

    cudaFuncSetAttribute(attn_kernel, cudaFuncAttributeMaxDynamicSharedMemorySize, SMEM_BYTES);

    qproj_kernel<<<dim3(96, 2), 256>>>(z, Wq, bq);
    attn_kernel<<<dim3(NSPLIT, B_), 256, SMEM_BYTES>>>(x);
    outproj_kernel<<<192, 256>>>(z, Wo, bo, out);
}

// round 6
// speedup vs baseline: 1.5422x; 1.2273x over previous
#include <cuda_runtime.h>
#include <cstdint>
#include <cstddef>

// ---------------- problem constants ----------------
#define B_      128
#define C_      64
#define HW_     3136
#define M_      6
#define D_      192
#define HEADS_  8
#define INNER_  512
#define ROWS_   48          // HEADS_*M_
#define NSPLIT  4
#define LEN_    784         // HW_/NSPLIT
#define TILE_N  112         // 784 = 7*112 exactly -> no tail masking
#define NTILES  7
#define XT_STRIDE 66        // xsT [112][66]: even (8B-aligned rows), 2-way write conflicts only
#define NEG_INF (-3.0e38f)

// smem: qs2 6144 + xs 64*112 + xsT 112*66 + ss 48*112 + 3*48
#define SMEM_FLOATS (6144 + 64*TILE_N + TILE_N*XT_STRIDE + ROWS_*TILE_N + 3*ROWS_)
#define SMEM_BYTES  (SMEM_FLOATS * 4)

// ---------------- scratch (__device__ globals) ----------------
__device__ float g_qbuf[B_ * M_ * INNER_];
__device__ float g_pm[B_ * ROWS_ * NSPLIT];
__device__ float g_pl[B_ * ROWS_ * NSPLIT];
__device__ float g_po[(size_t)B_ * ROWS_ * NSPLIT * C_];

typedef unsigned long long u64;

__device__ __forceinline__ void ffma2(u64 &d, u64 a, u64 b) {
    asm("fma.rn.f32x2 %0, %1, %2, %0;" : "+l"(d) : "l"(a), "l"(b));
}
__device__ __forceinline__ u64 fmul2(u64 a, u64 b) {
    u64 d; asm("mul.rn.f32x2 %0, %1, %2;" : "=l"(d) : "l"(a), "l"(b)); return d;
}
__device__ __forceinline__ u64 pack2(float lo, float hi) {
    return ((u64)__float_as_uint(hi) << 32) | (u64)__float_as_uint(lo);
}
__device__ __forceinline__ float lo2(u64 v) { return __uint_as_float((unsigned)v); }
__device__ __forceinline__ float hi2(u64 v) { return __uint_as_float((unsigned)(v >> 32)); }

// ============================================================================
// Kernel 1: q = (z @ Wq + bq) * 0.125 -> g_qbuf. grid (192,4) x 128thr = 768
// CTAs (5.2/SM) so L2 latency is hidden; k unrolled x8 for MLP.
// ============================================================================
__global__ void __launch_bounds__(128) qproj_kernel(
    const float* __restrict__ z, const float* __restrict__ Wq,
    const float* __restrict__ bq)
{
    __shared__ float zsh[4 * 192];
    const int t  = threadIdx.x;
    const int e0 = blockIdx.x * 4;
    const int d  = blockIdx.y * 128 + t;

    for (int idx = t; idx < 4 * 192; idx += 128)
        zsh[idx] = z[(size_t)e0 * 192 + idx];
    __syncthreads();

    float acc[4];
#pragma unroll
    for (int r = 0; r < 4; r++) acc[r] = 0.f;

    for (int k0 = 0; k0 < 192; k0 += 8) {
        float w[8];
#pragma unroll
        for (int j = 0; j < 8; j++)
            w[j] = Wq[(size_t)(k0 + j) * 512 + d];
#pragma unroll
        for (int j = 0; j < 8; j++)
#pragma unroll
            for (int r = 0; r < 4; r++)
                acc[r] += zsh[r * 192 + k0 + j] * w[j];
    }
    const float bv = bq[d];
#pragma unroll
    for (int r = 0; r < 4; r++)
        g_qbuf[(size_t)(e0 + r) * 512 + d] = (acc[r] + bv) * 0.125f;
}

// ============================================================================
// Kernel 2: fused attention, flash-decoding. grid (NSPLIT, B), 256 thr, occ 2.
// Tile = [64 c][112 n]. Dual layout: xs (c-major) for phase1, xsT (n-major,
// stride 66) for conflict-free phase3. Phase3 pairs over c (oacc = c-pair u64),
// P duplicated in registers. q flat-view: q[b][r*64+c], r = h*6+m.
// ============================================================================
__global__ void __launch_bounds__(256, 2) attn_kernel(const float* __restrict__ x)
{
    extern __shared__ float sm[];
    float* qs2 = sm;                         // 48*64 duplicated pairs (6144 floats)
    float* xs  = sm + 6144;                  // [64][112]
    float* xsT = xs + 64 * TILE_N;           // [112][66]
    float* ss  = xsT + TILE_N * XT_STRIDE;   // [48][112]
    float* smm = ss + ROWS_ * TILE_N;        // 48
    float* sml = smm + ROWS_;                // 48
    float* smc = sml + ROWS_;                // 48

    const int t     = threadIdx.x;
    const int split = blockIdx.x;
    const int b     = blockIdx.y;
    const int n0    = split * LEN_;
    const int rg    = t >> 5;                // warp = row-group (6 rows)
    const int lane  = t & 31;

    if (t < ROWS_) { smm[t] = NEG_INF; sml[t] = 0.f; }

    u64* qs2v = (u64*)qs2;
    for (int e = t; e < ROWS_ * C_; e += 256) {
        float qv = g_qbuf[(size_t)b * (ROWS_ * C_) + e];
        qs2v[e] = pack2(qv, qv);
    }

    u64 oacc[6];                              // (O[r][2*lane], O[r][2*lane+1])
#pragma unroll
    for (int i = 0; i < 6; i++) oacc[i] = 0ull;
    __syncthreads();

    // transpose-pass mapping (constant per thread)
    const int ttn   = t & 127;                // n index
    const int chalf = (t >> 7) * 32;          // c base: 0 or 32
    const bool tact = ttn < TILE_N;

    for (int tile = 0; tile < NTILES; tile++) {
        const int t0 = tile * TILE_N;

        // ---- load x tile [64][112]: 7 float4 per thread, no bounds checks ----
#pragma unroll
        for (int it = 0; it < 7; it++) {
            int idx = t + it * 256;           // < 1792
            int c = idx / 28, j = idx % 28;
            int nl = j * 4;
            float4 v = *(const float4*)&x[((size_t)b * C_ + c) * HW_ + n0 + t0 + nl];
            *(float4*)&xs[c * TILE_N + nl] = v;
        }
        __syncthreads();

        // ---- phase 1: S[48][112] = Q @ Xtile (lanes 0..27, 4 n each) ----
        if (lane < 28) {
            u64 sacc[6][2];
#pragma unroll
            for (int i = 0; i < 6; i++) { sacc[i][0] = 0ull; sacc[i][1] = 0ull; }
            const int nb = lane * 4;
#pragma unroll 4
            for (int c = 0; c < 64; c += 2) {
                ulonglong2 xva = *(const ulonglong2*)&xs[c * TILE_N + nb];        // c
                ulonglong2 xvb = *(const ulonglong2*)&xs[(c + 1) * TILE_N + nb];  // c+1
#pragma unroll
                for (int i = 0; i < 6; i++) {
                    ulonglong2 qp = *(const ulonglong2*)&qs2v[(rg * 6 + i) * 64 + c];
                    ffma2(sacc[i][0], qp.x, xva.x);
                    ffma2(sacc[i][1], qp.x, xva.y);
                    ffma2(sacc[i][0], qp.y, xvb.x);
                    ffma2(sacc[i][1], qp.y, xvb.y);
                }
            }
#pragma unroll
            for (int i = 0; i < 6; i++) {
                int r = rg * 6 + i;
                *(float4*)&ss[r * TILE_N + nb] =
                    make_float4(lo2(sacc[i][0]), hi2(sacc[i][0]),
                                lo2(sacc[i][1]), hi2(sacc[i][1]));
            }
        }
        __syncwarp();

        // ---- phase 2: online softmax (warp-private rows) ----
        {
#pragma unroll
            for (int i = 0; i < 6; i++) {
                int r = rg * 6 + i;
                float v0 = ss[r * TILE_N + lane];
                float v1 = ss[r * TILE_N + lane + 32];
                float v2 = ss[r * TILE_N + lane + 64];
                float v3 = (lane < 16) ? ss[r * TILE_N + lane + 96] : NEG_INF;
                float ml = fmaxf(fmaxf(v0, v1), fmaxf(v2, v3));
#pragma unroll
                for (int off = 16; off; off >>= 1)
                    ml = fmaxf(ml, __shfl_xor_sync(0xffffffffu, ml, off));
                float mprev = smm[r];
                float mnew  = fmaxf(mprev, ml);
                float cr    = __expf(mprev - mnew);
                float p0 = __expf(v0 - mnew);
                float p1 = __expf(v1 - mnew);
                float p2 = __expf(v2 - mnew);
                float p3 = __expf(v3 - mnew);
                ss[r * TILE_N + lane]      = p0;
                ss[r * TILE_N + lane + 32] = p1;
                ss[r * TILE_N + lane + 64] = p2;
                if (lane < 16) ss[r * TILE_N + lane + 96] = p3;
                float sl = (p0 + p1) + (p2 + p3);
#pragma unroll
                for (int off = 16; off; off >>= 1)
                    sl += __shfl_xor_sync(0xffffffffu, sl, off);
                if (lane == 0) {
                    sml[r] = sml[r] * cr + sl;
                    smm[r] = mnew;
                    smc[r] = cr;
                }
            }
        }

        // ---- transpose pass: xs[c][n] -> xsT[n][c] (lane->n: 2-way writes) ----
        if (tact) {
#pragma unroll 4
            for (int cc = 0; cc < 32; cc++) {
                int c = chalf + cc;
                xsT[ttn * XT_STRIDE + c] = xs[c * TILE_N + ttn];
            }
        }
        __syncthreads();   // xsT complete for all warps

        // ---- phase 3: O[r][c-pair] += P @ X^T (conflict-free xsT reads) ----
        {
#pragma unroll
            for (int i = 0; i < 6; i++) {
                float cr = smc[rg * 6 + i];
                oacc[i] = fmul2(oacc[i], pack2(cr, cr));
            }
            const int cp = lane * 2;
#pragma unroll 4
            for (int n = 0; n < TILE_N; n += 2) {
                u64 xvA = *(const u64*)&xsT[n * XT_STRIDE + cp];
                u64 xvB = *(const u64*)&xsT[(n + 1) * XT_STRIDE + cp];
#pragma unroll
                for (int i = 0; i < 6; i++) {
                    u64 pp = *(const u64*)&ss[(rg * 6 + i) * TILE_N + n];
                    float pa = lo2(pp), pb = hi2(pp);
                    ffma2(oacc[i], pack2(pa, pa), xvA);
                    ffma2(oacc[i], pack2(pb, pb), xvB);
                }
            }
        }
        __syncthreads();   // xs/xsT about to be overwritten
    }

    // ---- epilogue: write split partials (c-paired, direct STG.64) ----
#pragma unroll
    for (int i = 0; i < 6; i++) {
        int r = rg * 6 + i;
        size_t base = ((size_t)(b * ROWS_ + r) * NSPLIT + split) * C_;
        *(u64*)&g_po[base + lane * 2] = oacc[i];
    }
    if (t < ROWS_) {
        g_pm[(b * ROWS_ + t) * NSPLIT + split] = smm[t];
        g_pl[(b * ROWS_ + t) * NSPLIT + split] = sml[t];
    }
}

// ============================================================================
// Kernel 3: combine splits + out = res @ Wo + bo + z.
// grid (192 row-groups of 4, 3 d-groups of 64) x 256 thr = 576 CTAs.
// ============================================================================
__global__ void __launch_bounds__(256) outproj_kernel(
    const float* __restrict__ z, const float* __restrict__ Wo,
    const float* __restrict__ bo, float* __restrict__ out)
{
    __shared__ float res[4 * 512];
    __shared__ float cw[32][6];          // per (rl,h): w0..w3, rinv
    const int t  = threadIdx.x;
    const int e0 = blockIdx.x * 4;
    const int d0 = blockIdx.y * 64;

    if (t < 32) {                         // per (row, head) scalars
        int rl = t >> 3, h = t & 7;
        int e = e0 + rl;
        int bb = e / 6, m = e % 6;
        int base = (bb * ROWS_ + h * 6 + m) * NSPLIT;
        float m0 = g_pm[base], m1 = g_pm[base + 1], m2 = g_pm[base + 2], m3 = g_pm[base + 3];
        float Mx = fmaxf(fmaxf(m0, m1), fmaxf(m2, m3));
        float w0 = __expf(m0 - Mx), w1 = __expf(m1 - Mx);
        float w2 = __expf(m2 - Mx), w3 = __expf(m3 - Mx);
        float L = g_pl[base] * w0 + g_pl[base + 1] * w1
                + g_pl[base + 2] * w2 + g_pl[base + 3] * w3;
        cw[t][0] = w0; cw[t][1] = w1; cw[t][2] = w2; cw[t][3] = w3;
        cw[t][4] = 1.0f / L;
    }
    __syncthreads();

    // combine: res[rl][h*64+c] = sum_s po_s * w_s * rinv  (8 elements/thread)
#pragma unroll
    for (int k = 0; k < 8; k++) {
        int idx = t + k * 256;            // < 2048
        int rl = idx >> 9, j = idx & 511;
        int h = j >> 6, c = j & 63;
        int e = e0 + rl;
        int bb = e / 6, m = e % 6;
        size_t base = (size_t)((bb * ROWS_ + h * 6 + m) * NSPLIT) * C_;
        float w0 = cw[rl * 8 + h][0], w1 = cw[rl * 8 + h][1];
        float w2 = cw[rl * 8 + h][2], w3 = cw[rl * 8 + h][3];
        float ri = cw[rl * 8 + h][4];
        float v = g_po[base + c] * w0 + g_po[base + C_ + c] * w1
                + g_po[base + 2 * C_ + c] * w2 + g_po[base + 3 * C_ + c] * w3;
        res[idx] = v * ri;
    }
    __syncthreads();

    // GEMM: each thread one (row, d)
    const int row = t >> 6;
    const int dd  = d0 + (t & 63);
    float acc = bo[dd] + z[(size_t)(e0 + row) * D_ + dd];
    for (int i0 = 0; i0 < 512; i0 += 8) {
        float w[8], rr[8];
#pragma unroll
        for (int j = 0; j < 8; j++) {
            w[j]  = Wo[(size_t)(i0 + j) * D_ + dd];
            rr[j] = res[row * 512 + i0 + j];
        }
#pragma unroll
        for (int j = 0; j < 8; j++)
            acc += rr[j] * w[j];
    }
    out[(size_t)(e0 + row) * D_ + dd] = acc;
}

// ============================================================================
extern "C" void kernel_launch(void* const* d_in, const int* in_sizes, int n_in,
                              void* d_out, int out_size)
{
    (void)in_sizes; (void)n_in; (void)out_size;
    const float* x  = (const float*)d_in[0];
    const float* z  = (const float*)d_in[1];
    const float* Wq = (const float*)d_in[2];
    const float* bq = (const float*)d_in[3];
    const float* Wo = (const float*)d_in[4];
    const float* bo = (const float*)d_in[5];
    float* out = (float*)d_out;

    cudaFuncSetAttribute(attn_kernel, cudaFuncAttributeMaxDynamicSharedMemorySize, SMEM_BYTES);

    qproj_kernel<<<dim3(192, 4), 128>>>(z, Wq, bq);
    attn_kernel<<<dim3(NSPLIT, B_), 256, SMEM_BYTES>>>(x);
    outproj_kernel<<<dim3(192, 3), 256>>>(z, Wo, bo, out);
}

// round 7
// speedup vs baseline: 1.5436x; 1.0009x over previous
#include <cuda_runtime.h>
#include <cstdint>
#include <cstddef>

// ---------------- problem constants ----------------
#define B_      128
#define C_      64
#define HW_     3136
#define M_      6
#define D_      192
#define HEADS_  8
#define INNER_  512
#define ROWS_   48          // HEADS_*M_
#define NSPLIT  4
#define LEN_    784         // HW_/NSPLIT
#define TILE_N  112         // 784 = 7*112 exactly -> no tail masking
#define NTILES  7
#define XT_STRIDE 66        // xsT [112][66]: even (8B-aligned rows), 2-way write conflicts only
#define NEG_INF (-3.0e38f)

// smem: qs2 6144 + xs 64*112 + xsT 112*66 + ss 48*112 + 3*48
#define SMEM_FLOATS (6144 + 64*TILE_N + TILE_N*XT_STRIDE + ROWS_*TILE_N + 3*ROWS_)
#define SMEM_BYTES  (SMEM_FLOATS * 4)

// ---------------- scratch (__device__ globals) ----------------
__device__ float g_qbuf[B_ * M_ * INNER_];
__device__ float g_pm[B_ * ROWS_ * NSPLIT];
__device__ float g_pl[B_ * ROWS_ * NSPLIT];
__device__ float g_po[(size_t)B_ * ROWS_ * NSPLIT * C_];

typedef unsigned long long u64;

__device__ __forceinline__ void ffma2(u64 &d, u64 a, u64 b) {
    asm("fma.rn.f32x2 %0, %1, %2, %0;" : "+l"(d) : "l"(a), "l"(b));
}
__device__ __forceinline__ u64 fmul2(u64 a, u64 b) {
    u64 d; asm("mul.rn.f32x2 %0, %1, %2;" : "=l"(d) : "l"(a), "l"(b)); return d;
}
__device__ __forceinline__ u64 pack2(float lo, float hi) {
    return ((u64)__float_as_uint(hi) << 32) | (u64)__float_as_uint(lo);
}
__device__ __forceinline__ float lo2(u64 v) { return __uint_as_float((unsigned)v); }
__device__ __forceinline__ float hi2(u64 v) { return __uint_as_float((unsigned)(v >> 32)); }

// ============================================================================
// Kernel 1: q = (z @ Wq + bq) * 0.125 -> g_qbuf. grid (192,4) x 128thr = 768
// CTAs (5.2/SM) so L2 latency is hidden; k unrolled x8 for MLP.
// ============================================================================
__global__ void __launch_bounds__(128) qproj_kernel(
    const float* __restrict__ z, const float* __restrict__ Wq,
    const float* __restrict__ bq)
{
    __shared__ float zsh[4 * 192];
    const int t  = threadIdx.x;
    const int e0 = blockIdx.x * 4;
    const int d  = blockIdx.y * 128 + t;

    for (int idx = t; idx < 4 * 192; idx += 128)
        zsh[idx] = z[(size_t)e0 * 192 + idx];
    __syncthreads();

    float acc[4];
#pragma unroll
    for (int r = 0; r < 4; r++) acc[r] = 0.f;

    for (int k0 = 0; k0 < 192; k0 += 8) {
        float w[8];
#pragma unroll
        for (int j = 0; j < 8; j++)
            w[j] = Wq[(size_t)(k0 + j) * 512 + d];
#pragma unroll
        for (int j = 0; j < 8; j++)
#pragma unroll
            for (int r = 0; r < 4; r++)
                acc[r] += zsh[r * 192 + k0 + j] * w[j];
    }
    const float bv = bq[d];
#pragma unroll
    for (int r = 0; r < 4; r++)
        g_qbuf[(size_t)(e0 + r) * 512 + d] = (acc[r] + bv) * 0.125f;
}

// ============================================================================
// Kernel 2: fused attention, flash-decoding. grid (NSPLIT, B), 256 thr, occ 2.
// Tile = [64 c][112 n]. Dual layout: xs (c-major) for phase1, xsT (n-major,
// stride 66) for conflict-free phase3. Phase3 pairs over c (oacc = c-pair u64),
// P duplicated in registers. q flat-view: q[b][r*64+c], r = h*6+m.
// ============================================================================
__global__ void __launch_bounds__(256, 2) attn_kernel(const float* __restrict__ x)
{
    extern __shared__ float sm[];
    float* qs2 = sm;                         // 48*64 duplicated pairs (6144 floats)
    float* xs  = sm + 6144;                  // [64][112]
    float* xsT = xs + 64 * TILE_N;           // [112][66]
    float* ss  = xsT + TILE_N * XT_STRIDE;   // [48][112]
    float* smm = ss + ROWS_ * TILE_N;        // 48
    float* sml = smm + ROWS_;                // 48
    float* smc = sml + ROWS_;                // 48

    const int t     = threadIdx.x;
    const int split = blockIdx.x;
    const int b     = blockIdx.y;
    const int n0    = split * LEN_;
    const int rg    = t >> 5;                // warp = row-group (6 rows)
    const int lane  = t & 31;

    if (t < ROWS_) { smm[t] = NEG_INF; sml[t] = 0.f; }

    u64* qs2v = (u64*)qs2;
    for (int e = t; e < ROWS_ * C_; e += 256) {
        float qv = g_qbuf[(size_t)b * (ROWS_ * C_) + e];
        qs2v[e] = pack2(qv, qv);
    }

    u64 oacc[6];                              // (O[r][2*lane], O[r][2*lane+1])
#pragma unroll
    for (int i = 0; i < 6; i++) oacc[i] = 0ull;
    __syncthreads();

    // transpose-pass mapping (constant per thread)
    const int ttn   = t & 127;                // n index
    const int chalf = (t >> 7) * 32;          // c base: 0 or 32
    const bool tact = ttn < TILE_N;

    for (int tile = 0; tile < NTILES; tile++) {
        const int t0 = tile * TILE_N;

        // ---- load x tile [64][112]: 7 float4 per thread, no bounds checks ----
#pragma unroll
        for (int it = 0; it < 7; it++) {
            int idx = t + it * 256;           // < 1792
            int c = idx / 28, j = idx % 28;
            int nl = j * 4;
            float4 v = *(const float4*)&x[((size_t)b * C_ + c) * HW_ + n0 + t0 + nl];
            *(float4*)&xs[c * TILE_N + nl] = v;
        }
        __syncthreads();

        // ---- phase 1: S[48][112] = Q @ Xtile (lanes 0..27, 4 n each) ----
        if (lane < 28) {
            u64 sacc[6][2];
#pragma unroll
            for (int i = 0; i < 6; i++) { sacc[i][0] = 0ull; sacc[i][1] = 0ull; }
            const int nb = lane * 4;
#pragma unroll 4
            for (int c = 0; c < 64; c += 2) {
                ulonglong2 xva = *(const ulonglong2*)&xs[c * TILE_N + nb];        // c
                ulonglong2 xvb = *(const ulonglong2*)&xs[(c + 1) * TILE_N + nb];  // c+1
#pragma unroll
                for (int i = 0; i < 6; i++) {
                    ulonglong2 qp = *(const ulonglong2*)&qs2v[(rg * 6 + i) * 64 + c];
                    ffma2(sacc[i][0], qp.x, xva.x);
                    ffma2(sacc[i][1], qp.x, xva.y);
                    ffma2(sacc[i][0], qp.y, xvb.x);
                    ffma2(sacc[i][1], qp.y, xvb.y);
                }
            }
#pragma unroll
            for (int i = 0; i < 6; i++) {
                int r = rg * 6 + i;
                *(float4*)&ss[r * TILE_N + nb] =
                    make_float4(lo2(sacc[i][0]), hi2(sacc[i][0]),
                                lo2(sacc[i][1]), hi2(sacc[i][1]));
            }
        }
        __syncwarp();

        // ---- phase 2: online softmax (warp-private rows) ----
        {
#pragma unroll
            for (int i = 0; i < 6; i++) {
                int r = rg * 6 + i;
                float v0 = ss[r * TILE_N + lane];
                float v1 = ss[r * TILE_N + lane + 32];
                float v2 = ss[r * TILE_N + lane + 64];
                float v3 = (lane < 16) ? ss[r * TILE_N + lane + 96] : NEG_INF;
                float ml = fmaxf(fmaxf(v0, v1), fmaxf(v2, v3));
#pragma unroll
                for (int off = 16; off; off >>= 1)
                    ml = fmaxf(ml, __shfl_xor_sync(0xffffffffu, ml, off));
                float mprev = smm[r];
                float mnew  = fmaxf(mprev, ml);
                float cr    = __expf(mprev - mnew);
                float p0 = __expf(v0 - mnew);
                float p1 = __expf(v1 - mnew);
                float p2 = __expf(v2 - mnew);
                float p3 = __expf(v3 - mnew);
                ss[r * TILE_N + lane]      = p0;
                ss[r * TILE_N + lane + 32] = p1;
                ss[r * TILE_N + lane + 64] = p2;
                if (lane < 16) ss[r * TILE_N + lane + 96] = p3;
                float sl = (p0 + p1) + (p2 + p3);
#pragma unroll
                for (int off = 16; off; off >>= 1)
                    sl += __shfl_xor_sync(0xffffffffu, sl, off);
                if (lane == 0) {
                    sml[r] = sml[r] * cr + sl;
                    smm[r] = mnew;
                    smc[r] = cr;
                }
            }
        }

        // ---- transpose pass: xs[c][n] -> xsT[n][c] (lane->n: 2-way writes) ----
        if (tact) {
#pragma unroll 4
            for (int cc = 0; cc < 32; cc++) {
                int c = chalf + cc;
                xsT[ttn * XT_STRIDE + c] = xs[c * TILE_N + ttn];
            }
        }
        __syncthreads();   // xsT complete for all warps

        // ---- phase 3: O[r][c-pair] += P @ X^T (conflict-free xsT reads) ----
        {
#pragma unroll
            for (int i = 0; i < 6; i++) {
                float cr = smc[rg * 6 + i];
                oacc[i] = fmul2(oacc[i], pack2(cr, cr));
            }
            const int cp = lane * 2;
#pragma unroll 4
            for (int n = 0; n < TILE_N; n += 2) {
                u64 xvA = *(const u64*)&xsT[n * XT_STRIDE + cp];
                u64 xvB = *(const u64*)&xsT[(n + 1) * XT_STRIDE + cp];
#pragma unroll
                for (int i = 0; i < 6; i++) {
                    u64 pp = *(const u64*)&ss[(rg * 6 + i) * TILE_N + n];
                    float pa = lo2(pp), pb = hi2(pp);
                    ffma2(oacc[i], pack2(pa, pa), xvA);
                    ffma2(oacc[i], pack2(pb, pb), xvB);
                }
            }
        }
        __syncthreads();   // xs/xsT about to be overwritten
    }

    // ---- epilogue: write split partials (c-paired, direct STG.64) ----
#pragma unroll
    for (int i = 0; i < 6; i++) {
        int r = rg * 6 + i;
        size_t base = ((size_t)(b * ROWS_ + r) * NSPLIT + split) * C_;
        *(u64*)&g_po[base + lane * 2] = oacc[i];
    }
    if (t < ROWS_) {
        g_pm[(b * ROWS_ + t) * NSPLIT + split] = smm[t];
        g_pl[(b * ROWS_ + t) * NSPLIT + split] = sml[t];
    }
}

// ============================================================================
// Kernel 3: combine splits + out = res @ Wo + bo + z.
// grid (192 row-groups of 4, 3 d-groups of 64) x 256 thr = 576 CTAs.
// ============================================================================
__global__ void __launch_bounds__(256) outproj_kernel(
    const float* __restrict__ z, const float* __restrict__ Wo,
    const float* __restrict__ bo, float* __restrict__ out)
{
    __shared__ float res[4 * 512];
    __shared__ float cw[32][6];          // per (rl,h): w0..w3, rinv
    const int t  = threadIdx.x;
    const int e0 = blockIdx.x * 4;
    const int d0 = blockIdx.y * 64;

    if (t < 32) {                         // per (row, head) scalars
        int rl = t >> 3, h = t & 7;
        int e = e0 + rl;
        int bb = e / 6, m = e % 6;
        int base = (bb * ROWS_ + h * 6 + m) * NSPLIT;
        float m0 = g_pm[base], m1 = g_pm[base + 1], m2 = g_pm[base + 2], m3 = g_pm[base + 3];
        float Mx = fmaxf(fmaxf(m0, m1), fmaxf(m2, m3));
        float w0 = __expf(m0 - Mx), w1 = __expf(m1 - Mx);
        float w2 = __expf(m2 - Mx), w3 = __expf(m3 - Mx);
        float L = g_pl[base] * w0 + g_pl[base + 1] * w1
                + g_pl[base + 2] * w2 + g_pl[base + 3] * w3;
        cw[t][0] = w0; cw[t][1] = w1; cw[t][2] = w2; cw[t][3] = w3;
        cw[t][4] = 1.0f / L;
    }
    __syncthreads();

    // combine: res[rl][h*64+c] = sum_s po_s * w_s * rinv  (8 elements/thread)
#pragma unroll
    for (int k = 0; k < 8; k++) {
        int idx = t + k * 256;            // < 2048
        int rl = idx >> 9, j = idx & 511;
        int h = j >> 6, c = j & 63;
        int e = e0 + rl;
        int bb = e / 6, m = e % 6;
        size_t base = (size_t)((bb * ROWS_ + h * 6 + m) * NSPLIT) * C_;
        float w0 = cw[rl * 8 + h][0], w1 = cw[rl * 8 + h][1];
        float w2 = cw[rl * 8 + h][2], w3 = cw[rl * 8 + h][3];
        float ri = cw[rl * 8 + h][4];
        float v = g_po[base + c] * w0 + g_po[base + C_ + c] * w1
                + g_po[base + 2 * C_ + c] * w2 + g_po[base + 3 * C_ + c] * w3;
        res[idx] = v * ri;
    }
    __syncthreads();

    // GEMM: each thread one (row, d)
    const int row = t >> 6;
    const int dd  = d0 + (t & 63);
    float acc = bo[dd] + z[(size_t)(e0 + row) * D_ + dd];
    for (int i0 = 0; i0 < 512; i0 += 8) {
        float w[8], rr[8];
#pragma unroll
        for (int j = 0; j < 8; j++) {
            w[j]  = Wo[(size_t)(i0 + j) * D_ + dd];
            rr[j] = res[row * 512 + i0 + j];
        }
#pragma unroll
        for (int j = 0; j < 8; j++)
            acc += rr[j] * w[j];
    }
    out[(size_t)(e0 + row) * D_ + dd] = acc;
}

// ============================================================================
extern "C" void kernel_launch(void* const* d_in, const int* in_sizes, int n_in,
                              void* d_out, int out_size)
{
    (void)in_sizes; (void)n_in; (void)out_size;
    const float* x  = (const float*)d_in[0];
    const float* z  = (const float*)d_in[1];
    const float* Wq = (const float*)d_in[2];
    const float* bq = (const float*)d_in[3];
    const float* Wo = (const float*)d_in[4];
    const float* bo = (const float*)d_in[5];
    float* out = (float*)d_out;

    cudaFuncSetAttribute(attn_kernel, cudaFuncAttributeMaxDynamicSharedMemorySize, SMEM_BYTES);

    qproj_kernel<<<dim3(192, 4), 128>>>(z, Wq, bq);
    attn_kernel<<<dim3(NSPLIT, B_), 256, SMEM_BYTES>>>(x);
    outproj_kernel<<<dim3(192, 3), 256>>>(z, Wo, bo, out);
}

// round 8
// speedup vs baseline: 1.9942x; 1.2919x over previous
#include <cuda_runtime.h>
#include <cstdint>
#include <cstddef>

// ---------------- problem constants ----------------
#define B_      128
#define C_      64
#define HW_     3136
#define M_      6
#define D_      192
#define ROWS_   48          // heads*M
#define NSPLIT  4
#define LEN_    784         // HW_/NSPLIT
#define TILE_N  112         // 784 = 7*112 -> never any tail masking
#define NTILES  7
#define XSTR    116         // xs stride: 116*c mod 32 = {0,20,8,28,16,4,24,12} -> phase3 B conflict-free
#define SSTR    114         // ss stride: even (STS.64 ok), ~2-way worst case
#define NEG_INF (-3.0e38f)

#define SMEM_FLOATS (64*XSTR + ROWS_*SSTR + 3*ROWS_)
#define SMEM_BYTES  (SMEM_FLOATS * 4)

// ---------------- scratch ----------------
__device__ float g_qbuf[B_ * ROWS_ * C_];
__device__ float g_pm[B_ * ROWS_ * NSPLIT];
__device__ float g_pl[B_ * ROWS_ * NSPLIT];
__device__ float g_po[(size_t)B_ * ROWS_ * NSPLIT * C_];

typedef unsigned int uint32;

__device__ __forceinline__ uint32 f2tf32(float f) {
    uint32 r; asm("cvt.rna.tf32.f32 %0, %1;" : "=r"(r) : "f"(f)); return r;
}
// D(16x8,f32) += A(16x8,tf32) @ B(8x8,tf32)
__device__ __forceinline__ void mma_tf32(float* d, const uint32* a, uint32 b0, uint32 b1) {
    asm("mma.sync.aligned.m16n8k8.row.col.f32.tf32.tf32.f32 "
        "{%0,%1,%2,%3}, {%4,%5,%6,%7}, {%8,%9}, {%0,%1,%2,%3};"
        : "+f"(d[0]), "+f"(d[1]), "+f"(d[2]), "+f"(d[3])
        : "r"(a[0]), "r"(a[1]), "r"(a[2]), "r"(a[3]), "r"(b0), "r"(b1));
}

// ============================================================================
// Kernel 1: q = (z @ Wq + bq) * 0.125 -> g_qbuf. 96 CTAs x 8 rows, d-quad per
// thread (float4 Wq loads: 16 FMA per LDG.128), k unrolled x4 for MLP.
// ============================================================================
__global__ void __launch_bounds__(128) qproj_kernel(
    const float* __restrict__ z, const float* __restrict__ Wq,
    const float* __restrict__ bq)
{
    __shared__ float zsh[8 * 192];
    const int t  = threadIdx.x;
    const int e0 = blockIdx.x * 8;
    const int d0 = t * 4;

    for (int idx = t; idx < 8 * 192; idx += 128)
        zsh[idx] = z[(size_t)e0 * 192 + idx];
    __syncthreads();

    float acc[8][4];
#pragma unroll
    for (int r = 0; r < 8; r++)
#pragma unroll
        for (int j = 0; j < 4; j++) acc[r][j] = 0.f;

    for (int k0 = 0; k0 < 192; k0 += 4) {
        float4 w[4];
#pragma unroll
        for (int j = 0; j < 4; j++)
            w[j] = *(const float4*)&Wq[(size_t)(k0 + j) * 512 + d0];
#pragma unroll
        for (int j = 0; j < 4; j++)
#pragma unroll
            for (int r = 0; r < 8; r++) {
                float zv = zsh[r * 192 + k0 + j];
                acc[r][0] += zv * w[j].x;
                acc[r][1] += zv * w[j].y;
                acc[r][2] += zv * w[j].z;
                acc[r][3] += zv * w[j].w;
            }
    }
    float4 bv = *(const float4*)&bq[d0];
#pragma unroll
    for (int r = 0; r < 8; r++) {
        float4 o;
        o.x = (acc[r][0] + bv.x) * 0.125f;
        o.y = (acc[r][1] + bv.y) * 0.125f;
        o.z = (acc[r][2] + bv.z) * 0.125f;
        o.w = (acc[r][3] + bv.w) * 0.125f;
        *(float4*)&g_qbuf[(size_t)(e0 + r) * 512 + d0] = o;
    }
}

// ============================================================================
// Kernel 2: fused flash attention with tf32 mma.sync tensor-core GEMMs.
// grid (NSPLIT, B), 192 threads = 6 warps, occ 3.
// Phase1: warp (rg=w>>1, nh=w&1): S rows [rg*16,rg*16+16) x n-half (7 n8).
// Phase2: warp w: softmax rows [w*8, w*8+8), P re-rounded to tf32 in place.
// Phase3: warp (rg, ch=w&1): O rows rg*16.. x c-half (4 n8), K = 112 n.
// q flat-view: q[b][r*64+c], r = h*6+m.
// ============================================================================
__global__ void __launch_bounds__(192, 3) attn_kernel(const float* __restrict__ x)
{
    extern __shared__ float sm[];
    float* xs  = sm;                     // [64][XSTR]  (tf32-bit floats)
    float* ss  = xs + 64 * XSTR;         // [48][SSTR]  S then P
    float* smm = ss + ROWS_ * SSTR;      // 48
    float* sml = smm + ROWS_;            // 48
    float* smc = sml + ROWS_;            // 48
    uint32* xsu = (uint32*)xs;
    uint32* ssu = (uint32*)ss;

    const int t     = threadIdx.x;
    const int w     = t >> 5;            // 0..5
    const int lane  = t & 31;
    const int split = blockIdx.x;
    const int b     = blockIdx.y;
    const int n0    = split * LEN_;
    const int rg    = w >> 1;            // 0..2 (16-row group)
    const int half  = w & 1;             // n-half (phase1) / c-half (phase3)
    const int lq    = lane >> 2;         // 0..7
    const int lr    = lane & 3;          // 0..3

    // ---- Q fragments in registers (persist across tiles) ----
    uint32 aQ[8][4];
    {
        const float* qb = g_qbuf + (size_t)b * (ROWS_ * C_);
        int r0 = rg * 16 + lq;
#pragma unroll
        for (int kc = 0; kc < 8; kc++) {
            int k = kc * 8 + lr;
            aQ[kc][0] = f2tf32(qb[r0 * 64 + k]);
            aQ[kc][1] = f2tf32(qb[(r0 + 8) * 64 + k]);
            aQ[kc][2] = f2tf32(qb[r0 * 64 + k + 4]);
            aQ[kc][3] = f2tf32(qb[(r0 + 8) * 64 + k + 4]);
        }
    }

    if (t < ROWS_) { smm[t] = NEG_INF; sml[t] = 0.f; }

    float oacc[4][4];
#pragma unroll
    for (int nc = 0; nc < 4; nc++)
#pragma unroll
        for (int j = 0; j < 4; j++) oacc[nc][j] = 0.f;
    __syncthreads();

    for (int tile = 0; tile < NTILES; tile++) {
        const int t0 = tile * TILE_N;

        // ---- load x tile [64][112], convert to tf32 bits ----
#pragma unroll
        for (int it = 0; it < 10; it++) {
            int idx = t + it * 192;                 // float4 index, < 1792
            if (idx < 1792) {
                int c = idx / 28, j = idx % 28;
                int nl = j * 4;
                float4 v = *(const float4*)&x[((size_t)b * C_ + c) * HW_ + n0 + t0 + nl];
                uint4 u;
                u.x = f2tf32(v.x); u.y = f2tf32(v.y);
                u.z = f2tf32(v.z); u.w = f2tf32(v.w);
                *(uint4*)&xsu[c * XSTR + nl] = u;
            }
        }
        __syncthreads();

        // ---- phase 1: S = Q @ Xtile (tensor core) ----
        {
            const int nb = half * 56;
            float sacc[7][4];
#pragma unroll
            for (int nc = 0; nc < 7; nc++)
#pragma unroll
                for (int j = 0; j < 4; j++) sacc[nc][j] = 0.f;

#pragma unroll
            for (int kc = 0; kc < 8; kc++) {
                int bk = kc * 8 + lr;               // c index
                int bn = nb + lq;                    // n index
#pragma unroll
                for (int nc = 0; nc < 7; nc++) {
                    uint32 b0 = xsu[bk * XSTR + bn + nc * 8];
                    uint32 b1 = xsu[(bk + 4) * XSTR + bn + nc * 8];
                    mma_tf32(sacc[nc], aQ[kc], b0, b1);
                }
            }
            int sr = rg * 16 + lq;
            int sn = nb + 2 * lr;
#pragma unroll
            for (int nc = 0; nc < 7; nc++) {
                *(float2*)&ss[sr * SSTR + sn + nc * 8] =
                    make_float2(sacc[nc][0], sacc[nc][1]);
                *(float2*)&ss[(sr + 8) * SSTR + sn + nc * 8] =
                    make_float2(sacc[nc][2], sacc[nc][3]);
            }
        }
        __syncthreads();

        // ---- phase 2: online softmax, 8 rows per warp; P stored as tf32 ----
        {
#pragma unroll
            for (int i = 0; i < 8; i++) {
                int r = w * 8 + i;
                float v0 = ss[r * SSTR + lane];
                float v1 = ss[r * SSTR + lane + 32];
                float v2 = ss[r * SSTR + lane + 64];
                float v3 = (lane < 16) ? ss[r * SSTR + lane + 96] : NEG_INF;
                float ml = fmaxf(fmaxf(v0, v1), fmaxf(v2, v3));
#pragma unroll
                for (int off = 16; off; off >>= 1)
                    ml = fmaxf(ml, __shfl_xor_sync(0xffffffffu, ml, off));
                float mprev = smm[r];
                float mnew  = fmaxf(mprev, ml);
                float cr    = __expf(mprev - mnew);
                float p0 = __uint_as_float(f2tf32(__expf(v0 - mnew)));
                float p1 = __uint_as_float(f2tf32(__expf(v1 - mnew)));
                float p2 = __uint_as_float(f2tf32(__expf(v2 - mnew)));
                float p3 = __uint_as_float(f2tf32(__expf(v3 - mnew)));
                ss[r * SSTR + lane]      = p0;
                ss[r * SSTR + lane + 32] = p1;
                ss[r * SSTR + lane + 64] = p2;
                if (lane < 16) ss[r * SSTR + lane + 96] = p3;
                float sl = (p0 + p1) + ((lane < 16) ? (p2 + p3) : p2);
#pragma unroll
                for (int off = 16; off; off >>= 1)
                    sl += __shfl_xor_sync(0xffffffffu, sl, off);
                if (lane == 0) {
                    sml[r] = sml[r] * cr + sl;
                    smm[r] = mnew;
                    smc[r] = cr;
                }
            }
        }
        __syncthreads();

        // ---- phase 3: O += P @ Xtile^T (tensor core), K = 112 ----
        {
            float cr0 = smc[rg * 16 + lq];
            float cr8 = smc[rg * 16 + 8 + lq];
#pragma unroll
            for (int nc = 0; nc < 4; nc++) {
                oacc[nc][0] *= cr0; oacc[nc][1] *= cr0;
                oacc[nc][2] *= cr8; oacc[nc][3] *= cr8;
            }
            const int cb = half * 32;
            const int sr = rg * 16 + lq;
#pragma unroll
            for (int kc = 0; kc < 14; kc++) {
                int k = kc * 8 + lr;                 // n index (K dim)
                uint32 a[4];
                a[0] = ssu[sr * SSTR + k];
                a[1] = ssu[(sr + 8) * SSTR + k];
                a[2] = ssu[sr * SSTR + k + 4];
                a[3] = ssu[(sr + 8) * SSTR + k + 4];
#pragma unroll
                for (int nc = 0; nc < 4; nc++) {
                    int c = cb + nc * 8 + lq;
                    uint32 b0 = xsu[c * XSTR + k];
                    uint32 b1 = xsu[c * XSTR + k + 4];
                    mma_tf32(oacc[nc], a, b0, b1);
                }
            }
        }
        __syncthreads();
    }

    // ---- epilogue: write split partials ----
    {
        const int cb = half * 32;
        int r0 = rg * 16 + lq;
        size_t base0 = ((size_t)(b * ROWS_ + r0) * NSPLIT + split) * C_;
        size_t base8 = ((size_t)(b * ROWS_ + r0 + 8) * NSPLIT + split) * C_;
#pragma unroll
        for (int nc = 0; nc < 4; nc++) {
            int c = cb + nc * 8 + 2 * lr;
            *(float2*)&g_po[base0 + c] = make_float2(oacc[nc][0], oacc[nc][1]);
            *(float2*)&g_po[base8 + c] = make_float2(oacc[nc][2], oacc[nc][3]);
        }
    }
    if (t < ROWS_) {
        g_pm[(b * ROWS_ + t) * NSPLIT + split] = smm[t];
        g_pl[(b * ROWS_ + t) * NSPLIT + split] = sml[t];
    }
}

// ============================================================================
// Kernel 3: combine splits + out = res @ Wo + bo + z.  (unchanged from R7)
// ============================================================================
__global__ void __launch_bounds__(256) outproj_kernel(
    const float* __restrict__ z, const float* __restrict__ Wo,
    const float* __restrict__ bo, float* __restrict__ out)
{
    __shared__ float res[4 * 512];
    __shared__ float cw[32][6];
    const int t  = threadIdx.x;
    const int e0 = blockIdx.x * 4;
    const int d0 = blockIdx.y * 64;

    if (t < 32) {
        int rl = t >> 3, h = t & 7;
        int e = e0 + rl;
        int bb = e / 6, m = e % 6;
        int base = (bb * ROWS_ + h * 6 + m) * NSPLIT;
        float m0 = g_pm[base], m1 = g_pm[base + 1], m2 = g_pm[base + 2], m3 = g_pm[base + 3];
        float Mx = fmaxf(fmaxf(m0, m1), fmaxf(m2, m3));
        float w0 = __expf(m0 - Mx), w1 = __expf(m1 - Mx);
        float w2 = __expf(m2 - Mx), w3 = __expf(m3 - Mx);
        float L = g_pl[base] * w0 + g_pl[base + 1] * w1
                + g_pl[base + 2] * w2 + g_pl[base + 3] * w3;
        cw[t][0] = w0; cw[t][1] = w1; cw[t][2] = w2; cw[t][3] = w3;
        cw[t][4] = 1.0f / L;
    }
    __syncthreads();

#pragma unroll
    for (int k = 0; k < 8; k++) {
        int idx = t + k * 256;
        int rl = idx >> 9, j = idx & 511;
        int h = j >> 6, c = j & 63;
        int e = e0 + rl;
        int bb = e / 6, m = e % 6;
        size_t base = (size_t)((bb * ROWS_ + h * 6 + m) * NSPLIT) * C_;
        float w0 = cw[rl * 8 + h][0], w1 = cw[rl * 8 + h][1];
        float w2 = cw[rl * 8 + h][2], w3 = cw[rl * 8 + h][3];
        float ri = cw[rl * 8 + h][4];
        float v = g_po[base + c] * w0 + g_po[base + C_ + c] * w1
                + g_po[base + 2 * C_ + c] * w2 + g_po[base + 3 * C_ + c] * w3;
        res[idx] = v * ri;
    }
    __syncthreads();

    const int row = t >> 6;
    const int dd  = d0 + (t & 63);
    float acc = bo[dd] + z[(size_t)(e0 + row) * D_ + dd];
    for (int i0 = 0; i0 < 512; i0 += 8) {
        float wv[8], rr[8];
#pragma unroll
        for (int j = 0; j < 8; j++) {
            wv[j] = Wo[(size_t)(i0 + j) * D_ + dd];
            rr[j] = res[row * 512 + i0 + j];
        }
#pragma unroll
        for (int j = 0; j < 8; j++)
            acc += rr[j] * wv[j];
    }
    out[(size_t)(e0 + row) * D_ + dd] = acc;
}

// ============================================================================
extern "C" void kernel_launch(void* const* d_in, const int* in_sizes, int n_in,
                              void* d_out, int out_size)
{
    (void)in_sizes; (void)n_in; (void)out_size;
    const float* x  = (const float*)d_in[0];
    const float* z  = (const float*)d_in[1];
    const float* Wq = (const float*)d_in[2];
    const float* bq = (const float*)d_in[3];
    const float* Wo = (const float*)d_in[4];
    const float* bo = (const float*)d_in[5];
    float* out = (float*)d_out;

    cudaFuncSetAttribute(attn_kernel, cudaFuncAttributeMaxDynamicSharedMemorySize, SMEM_BYTES);

    qproj_kernel<<<96, 128>>>(z, Wq, bq);
    attn_kernel<<<dim3(NSPLIT, B_), 192, SMEM_BYTES>>>(x);
    outproj_kernel<<<dim3(192, 3), 256>>>(z, Wo, bo, out);
}

// round 10
// speedup vs baseline: 2.4537x; 1.2304x over previous
#include <cuda_runtime.h>
#include <cstdint>
#include <cstddef>

// ---------------- problem constants ----------------
#define B_      128
#define C_      64
#define HW_     3136
#define M_      6
#define D_      192
#define ROWS_   48          // heads*M
#define NSPLIT  4
#define LEN_    784         // HW_/NSPLIT
#define TILE_N  112         // 784 = 7*112 -> never any tail masking
#define NTILES  7
#define XSTR    116         // xs stride: phase3 B loads conflict-free
#define SSTR    114         // ss stride
#define NEG_INF (-3.0e38f)

#define SMEM_FLOATS (64*XSTR + ROWS_*SSTR + 3*ROWS_)
#define SMEM_BYTES  (SMEM_FLOATS * 4)

// qproj dynamic smem: z tile 32*192 + Wq tile 192*64 floats = 72 KB
#define QP_SMEM_BYTES ((32*192 + 192*64) * 4)

// ---------------- scratch ----------------
__device__ float g_qbuf[B_ * ROWS_ * C_];
__device__ float g_pm[B_ * ROWS_ * NSPLIT];
__device__ float g_pl[B_ * ROWS_ * NSPLIT];
__device__ float g_po[(size_t)B_ * ROWS_ * NSPLIT * C_];

typedef unsigned int uint32;

__device__ __forceinline__ uint32 f2tf32(float f) {
    uint32 r; asm("cvt.rna.tf32.f32 %0, %1;" : "=r"(r) : "f"(f)); return r;
}
// D(16x8,f32) += A(16x8,tf32) @ B(8x8,tf32)
__device__ __forceinline__ void mma_tf32(float* d, const uint32* a, uint32 b0, uint32 b1) {
    asm("mma.sync.aligned.m16n8k8.row.col.f32.tf32.tf32.f32 "
        "{%0,%1,%2,%3}, {%4,%5,%6,%7}, {%8,%9}, {%0,%1,%2,%3};"
        : "+f"(d[0]), "+f"(d[1]), "+f"(d[2]), "+f"(d[3])
        : "r"(a[0]), "r"(a[1]), "r"(a[2]), "r"(a[3]), "r"(b0), "r"(b1));
}

// ---- no-op launch: shifts ncu's -s 5 -c 1 capture onto attn_kernel ----
__global__ void noop_kernel() {}

// ============================================================================
// Kernel 1: q = (z @ Wq + bq) * 0.125 -> g_qbuf.
// Tiled smem GEMM: grid (24 rowblocks x 8 dblocks) = 192 CTAs, 256 thr.
// CTA tile 32 rows x 64 d; z tile (24KB) + Wq tile (48KB) in DYNAMIC smem
// (72KB > 48KB static limit), so the k-loop never touches global memory.
// Thread tile 4r x 2d; z reads warp-broadcast, w reads LDS.64 conflict-free.
// ============================================================================
__global__ void __launch_bounds__(256) qproj_kernel(
    const float* __restrict__ z, const float* __restrict__ Wq,
    const float* __restrict__ bq)
{
    extern __shared__ float qsm[];
    float* zsh = qsm;                     // [32][192]  24 KB
    float* wsh = qsm + 32 * 192;          // [192][64]  48 KB
    const int t  = threadIdx.x;
    const int e0 = blockIdx.x * 32;       // row base (of 768)
    const int d0 = blockIdx.y * 64;       // col base (of 512)

    // load z tile: contiguous 6144 floats
#pragma unroll
    for (int it = 0; it < 6; it++) {
        int idx = (t + it * 256) * 4;
        *(float4*)&zsh[idx] = *(const float4*)&z[(size_t)e0 * 192 + idx];
    }
    // load Wq tile: 192 rows x 16 float4
#pragma unroll
    for (int it = 0; it < 12; it++) {
        int idx = t + it * 256;           // < 3072
        int k = idx >> 4, c4 = (idx & 15) * 4;
        *(float4*)&wsh[k * 64 + c4] = *(const float4*)&Wq[(size_t)k * 512 + d0 + c4];
    }
    __syncthreads();

    const int r0 = (t >> 5) * 4;          // 4 rows per thread
    const int d  = (t & 31) * 2;          // 2 cols per thread
    float acc[4][2];
#pragma unroll
    for (int i = 0; i < 4; i++) { acc[i][0] = 0.f; acc[i][1] = 0.f; }

#pragma unroll 4
    for (int k = 0; k < 192; k++) {
        float2 w = *(const float2*)&wsh[k * 64 + d];
#pragma unroll
        for (int i = 0; i < 4; i++) {
            float zv = zsh[(r0 + i) * 192 + k];
            acc[i][0] += zv * w.x;
            acc[i][1] += zv * w.y;
        }
    }
    float2 bv = *(const float2*)&bq[d0 + d];
#pragma unroll
    for (int i = 0; i < 4; i++) {
        float2 o;
        o.x = (acc[i][0] + bv.x) * 0.125f;
        o.y = (acc[i][1] + bv.y) * 0.125f;
        *(float2*)&g_qbuf[(size_t)(e0 + r0 + i) * 512 + d0 + d] = o;
    }
}

// ============================================================================
// Kernel 2: fused flash attention with tf32 mma.sync (unchanged).
// grid (NSPLIT, B), 192 threads = 6 warps, occ 3.
// ============================================================================
__global__ void __launch_bounds__(192, 3) attn_kernel(const float* __restrict__ x)
{
    extern __shared__ float sm[];
    float* xs  = sm;                     // [64][XSTR]
    float* ss  = xs + 64 * XSTR;         // [48][SSTR]
    float* smm = ss + ROWS_ * SSTR;      // 48
    float* sml = smm + ROWS_;            // 48
    float* smc = sml + ROWS_;            // 48
    uint32* xsu = (uint32*)xs;
    uint32* ssu = (uint32*)ss;

    const int t     = threadIdx.x;
    const int w     = t >> 5;
    const int lane  = t & 31;
    const int split = blockIdx.x;
    const int b     = blockIdx.y;
    const int n0    = split * LEN_;
    const int rg    = w >> 1;
    const int half  = w & 1;
    const int lq    = lane >> 2;
    const int lr    = lane & 3;

    uint32 aQ[8][4];
    {
        const float* qb = g_qbuf + (size_t)b * (ROWS_ * C_);
        int r0 = rg * 16 + lq;
#pragma unroll
        for (int kc = 0; kc < 8; kc++) {
            int k = kc * 8 + lr;
            aQ[kc][0] = f2tf32(qb[r0 * 64 + k]);
            aQ[kc][1] = f2tf32(qb[(r0 + 8) * 64 + k]);
            aQ[kc][2] = f2tf32(qb[r0 * 64 + k + 4]);
            aQ[kc][3] = f2tf32(qb[(r0 + 8) * 64 + k + 4]);
        }
    }

    if (t < ROWS_) { smm[t] = NEG_INF; sml[t] = 0.f; }

    float oacc[4][4];
#pragma unroll
    for (int nc = 0; nc < 4; nc++)
#pragma unroll
        for (int j = 0; j < 4; j++) oacc[nc][j] = 0.f;
    __syncthreads();

    for (int tile = 0; tile < NTILES; tile++) {
        const int t0 = tile * TILE_N;

#pragma unroll
        for (int it = 0; it < 10; it++) {
            int idx = t + it * 192;
            if (idx < 1792) {
                int c = idx / 28, j = idx % 28;
                int nl = j * 4;
                float4 v = *(const float4*)&x[((size_t)b * C_ + c) * HW_ + n0 + t0 + nl];
                uint4 u;
                u.x = f2tf32(v.x); u.y = f2tf32(v.y);
                u.z = f2tf32(v.z); u.w = f2tf32(v.w);
                *(uint4*)&xsu[c * XSTR + nl] = u;
            }
        }
        __syncthreads();

        // ---- phase 1: S = Q @ Xtile ----
        {
            const int nb = half * 56;
            float sacc[7][4];
#pragma unroll
            for (int nc = 0; nc < 7; nc++)
#pragma unroll
                for (int j = 0; j < 4; j++) sacc[nc][j] = 0.f;

#pragma unroll
            for (int kc = 0; kc < 8; kc++) {
                int bk = kc * 8 + lr;
                int bn = nb + lq;
#pragma unroll
                for (int nc = 0; nc < 7; nc++) {
                    uint32 b0 = xsu[bk * XSTR + bn + nc * 8];
                    uint32 b1 = xsu[(bk + 4) * XSTR + bn + nc * 8];
                    mma_tf32(sacc[nc], aQ[kc], b0, b1);
                }
            }
            int sr = rg * 16 + lq;
            int sn = nb + 2 * lr;
#pragma unroll
            for (int nc = 0; nc < 7; nc++) {
                *(float2*)&ss[sr * SSTR + sn + nc * 8] =
                    make_float2(sacc[nc][0], sacc[nc][1]);
                *(float2*)&ss[(sr + 8) * SSTR + sn + nc * 8] =
                    make_float2(sacc[nc][2], sacc[nc][3]);
            }
        }
        __syncthreads();

        // ---- phase 2: online softmax ----
        {
#pragma unroll
            for (int i = 0; i < 8; i++) {
                int r = w * 8 + i;
                float v0 = ss[r * SSTR + lane];
                float v1 = ss[r * SSTR + lane + 32];
                float v2 = ss[r * SSTR + lane + 64];
                float v3 = (lane < 16) ? ss[r * SSTR + lane + 96] : NEG_INF;
                float ml = fmaxf(fmaxf(v0, v1), fmaxf(v2, v3));
#pragma unroll
                for (int off = 16; off; off >>= 1)
                    ml = fmaxf(ml, __shfl_xor_sync(0xffffffffu, ml, off));
                float mprev = smm[r];
                float mnew  = fmaxf(mprev, ml);
                float cr    = __expf(mprev - mnew);
                float p0 = __uint_as_float(f2tf32(__expf(v0 - mnew)));
                float p1 = __uint_as_float(f2tf32(__expf(v1 - mnew)));
                float p2 = __uint_as_float(f2tf32(__expf(v2 - mnew)));
                float p3 = __uint_as_float(f2tf32(__expf(v3 - mnew)));
                ss[r * SSTR + lane]      = p0;
                ss[r * SSTR + lane + 32] = p1;
                ss[r * SSTR + lane + 64] = p2;
                if (lane < 16) ss[r * SSTR + lane + 96] = p3;
                float sl = (p0 + p1) + ((lane < 16) ? (p2 + p3) : p2);
#pragma unroll
                for (int off = 16; off; off >>= 1)
                    sl += __shfl_xor_sync(0xffffffffu, sl, off);
                if (lane == 0) {
                    sml[r] = sml[r] * cr + sl;
                    smm[r] = mnew;
                    smc[r] = cr;
                }
            }
        }
        __syncthreads();

        // ---- phase 3: O += P @ Xtile^T ----
        {
            float cr0 = smc[rg * 16 + lq];
            float cr8 = smc[rg * 16 + 8 + lq];
#pragma unroll
            for (int nc = 0; nc < 4; nc++) {
                oacc[nc][0] *= cr0; oacc[nc][1] *= cr0;
                oacc[nc][2] *= cr8; oacc[nc][3] *= cr8;
            }
            const int cb = half * 32;
            const int sr = rg * 16 + lq;
#pragma unroll
            for (int kc = 0; kc < 14; kc++) {
                int k = kc * 8 + lr;
                uint32 a[4];
                a[0] = ssu[sr * SSTR + k];
                a[1] = ssu[(sr + 8) * SSTR + k];
                a[2] = ssu[sr * SSTR + k + 4];
                a[3] = ssu[(sr + 8) * SSTR + k + 4];
#pragma unroll
                for (int nc = 0; nc < 4; nc++) {
                    int c = cb + nc * 8 + lq;
                    uint32 b0 = xsu[c * XSTR + k];
                    uint32 b1 = xsu[c * XSTR + k + 4];
                    mma_tf32(oacc[nc], a, b0, b1);
                }
            }
        }
        __syncthreads();
    }

    {
        const int cb = half * 32;
        int r0 = rg * 16 + lq;
        size_t base0 = ((size_t)(b * ROWS_ + r0) * NSPLIT + split) * C_;
        size_t base8 = ((size_t)(b * ROWS_ + r0 + 8) * NSPLIT + split) * C_;
#pragma unroll
        for (int nc = 0; nc < 4; nc++) {
            int c = cb + nc * 8 + 2 * lr;
            *(float2*)&g_po[base0 + c] = make_float2(oacc[nc][0], oacc[nc][1]);
            *(float2*)&g_po[base8 + c] = make_float2(oacc[nc][2], oacc[nc][3]);
        }
    }
    if (t < ROWS_) {
        g_pm[(b * ROWS_ + t) * NSPLIT + split] = smm[t];
        g_pl[(b * ROWS_ + t) * NSPLIT + split] = sml[t];
    }
}

// ============================================================================
// Kernel 3: combine splits + out = res @ Wo + bo + z.  (unchanged)
// ============================================================================
__global__ void __launch_bounds__(256) outproj_kernel(
    const float* __restrict__ z, const float* __restrict__ Wo,
    const float* __restrict__ bo, float* __restrict__ out)
{
    __shared__ float res[4 * 512];
    __shared__ float cw[32][6];
    const int t  = threadIdx.x;
    const int e0 = blockIdx.x * 4;
    const int d0 = blockIdx.y * 64;

    if (t < 32) {
        int rl = t >> 3, h = t & 7;
        int e = e0 + rl;
        int bb = e / 6, m = e % 6;
        int base = (bb * ROWS_ + h * 6 + m) * NSPLIT;
        float m0 = g_pm[base], m1 = g_pm[base + 1], m2 = g_pm[base + 2], m3 = g_pm[base + 3];
        float Mx = fmaxf(fmaxf(m0, m1), fmaxf(m2, m3));
        float w0 = __expf(m0 - Mx), w1 = __expf(m1 - Mx);
        float w2 = __expf(m2 - Mx), w3 = __expf(m3 - Mx);
        float L = g_pl[base] * w0 + g_pl[base + 1] * w1
                + g_pl[base + 2] * w2 + g_pl[base + 3] * w3;
        cw[t][0] = w0; cw[t][1] = w1; cw[t][2] = w2; cw[t][3] = w3;
        cw[t][4] = 1.0f / L;
    }
    __syncthreads();

#pragma unroll
    for (int k = 0; k < 8; k++) {
        int idx = t + k * 256;
        int rl = idx >> 9, j = idx & 511;
        int h = j >> 6, c = j & 63;
        int e = e0 + rl;
        int bb = e / 6, m = e % 6;
        size_t base = (size_t)((bb * ROWS_ + h * 6 + m) * NSPLIT) * C_;
        float w0 = cw[rl * 8 + h][0], w1 = cw[rl * 8 + h][1];
        float w2 = cw[rl * 8 + h][2], w3 = cw[rl * 8 + h][3];
        float ri = cw[rl * 8 + h][4];
        float v = g_po[base + c] * w0 + g_po[base + C_ + c] * w1
                + g_po[base + 2 * C_ + c] * w2 + g_po[base + 3 * C_ + c] * w3;
        res[idx] = v * ri;
    }
    __syncthreads();

    const int row = t >> 6;
    const int dd  = d0 + (t & 63);
    float acc = bo[dd] + z[(size_t)(e0 + row) * D_ + dd];
    for (int i0 = 0; i0 < 512; i0 += 8) {
        float wv[8], rr[8];
#pragma unroll
        for (int j = 0; j < 8; j++) {
            wv[j] = Wo[(size_t)(i0 + j) * D_ + dd];
            rr[j] = res[row * 512 + i0 + j];
        }
#pragma unroll
        for (int j = 0; j < 8; j++)
            acc += rr[j] * wv[j];
    }
    out[(size_t)(e0 + row) * D_ + dd] = acc;
}

// ============================================================================
extern "C" void kernel_launch(void* const* d_in, const int* in_sizes, int n_in,
                              void* d_out, int out_size)
{
    (void)in_sizes; (void)n_in; (void)out_size;
    const float* x  = (const float*)d_in[0];
    const float* z  = (const float*)d_in[1];
    const float* Wq = (const float*)d_in[2];
    const float* bq = (const float*)d_in[3];
    const float* Wo = (const float*)d_in[4];
    const float* bo = (const float*)d_in[5];
    float* out = (float*)d_out;

    cudaFuncSetAttribute(attn_kernel,  cudaFuncAttributeMaxDynamicSharedMemorySize, SMEM_BYTES);
    cudaFuncSetAttribute(qproj_kernel, cudaFuncAttributeMaxDynamicSharedMemorySize, QP_SMEM_BYTES);

    noop_kernel<<<1, 32>>>();   // shifts ncu -s5-c1 capture onto attn_kernel
    qproj_kernel<<<dim3(24, 8), 256, QP_SMEM_BYTES>>>(z, Wq, bq);
    attn_kernel<<<dim3(NSPLIT, B_), 192, SMEM_BYTES>>>(x);
    outproj_kernel<<<dim3(192, 3), 256>>>(z, Wo, bo, out);
}